// round 4
// baseline (speedup 1.0000x reference)
#include <cuda_runtime.h>
#include <cstdint>

#define NG    1000
#define NODES 100
#define EDGES 1600
#define NTOT  100000
#define ETOT  1600000
#define HID   128
#define KTOP  40

// ---------------- scratch (device globals; no runtime allocation) ----------
__device__ float g_T [(size_t)NTOT * HID];
__device__ float g_X0[(size_t)NTOT * HID];
__device__ float g_X1[(size_t)NTOT * HID];
__device__ float g_X2[(size_t)NTOT * HID];
__device__ int   g_off [NG * 101];
__device__ int2  g_edge[ETOT];   // (src, bitcast norm)

// ---------------- helpers ---------------------------------------------------
__device__ __forceinline__ float acc_tanh(float x) {
    float xc = fminf(fmaxf(x, -10.f), 10.f);
    float e  = __expf(2.f * xc);
    return (e - 1.f) / (e + 1.f);
}
__device__ __forceinline__ float f2tf32f(float x) {
    uint32_t r;
    asm("cvt.rna.tf32.f32 %0, %1;" : "=r"(r) : "f"(x));
    return __uint_as_float(r);
}
__device__ __forceinline__ void mma_tf32(float c[4], const uint32_t a[4],
                                         const uint32_t b0, const uint32_t b1) {
    asm volatile(
        "mma.sync.aligned.m16n8k8.row.col.f32.tf32.tf32.f32 "
        "{%0,%1,%2,%3}, {%4,%5,%6,%7}, {%8,%9}, {%0,%1,%2,%3};\n"
        : "+f"(c[0]), "+f"(c[1]), "+f"(c[2]), "+f"(c[3])
        : "r"(a[0]), "r"(a[1]), "r"(a[2]), "r"(a[3]), "r"(b0), "r"(b1));
}

// ---------------- kernel 1: deterministic per-graph CSR --------------------
__global__ void __launch_bounds__(256) build_csr(const int* __restrict__ ei)
{
    __shared__ int   sdst[EDGES];
    __shared__ int   ssrc[EDGES];
    __shared__ int   deg[NODES];
    __shared__ float dinv[NODES];
    __shared__ int   offs[NODES + 1];

    const int g = blockIdx.x, tid = threadIdx.x;
    const int base = g * NODES;
    const int* srce = ei + (size_t)g * EDGES;
    const int* dste = ei + (size_t)ETOT + (size_t)g * EDGES;

    if (tid < NODES) deg[tid] = 0;
    __syncthreads();

    for (int e = tid; e < EDGES; e += 256) {
        int s = srce[e] - base;
        int d = dste[e] - base;
        ssrc[e] = s;
        sdst[e] = d;
        atomicAdd(&deg[d], 1);
    }
    __syncthreads();

    if (tid < NODES)
        dinv[tid] = deg[tid] > 0 ? rsqrtf((float)deg[tid]) : 0.f;
    if (tid == 0) {
        int acc = 0;
        for (int i = 0; i < NODES; i++) { offs[i] = acc; acc += deg[i]; }
        offs[NODES] = acc;
    }
    __syncthreads();

    if (tid <= NODES) g_off[g * 101 + tid] = offs[tid];

    const int lane = tid & 31, warp = tid >> 5;
    const size_t gb = (size_t)g * EDGES;
    for (int d = warp; d < NODES; d += 8) {
        int pos = offs[d];
        float dd = dinv[d];
        for (int eb = 0; eb < EDGES; eb += 32) {
            int e = eb + lane;
            bool m = (sdst[e] == d);
            unsigned mask = __ballot_sync(0xffffffffu, m);
            if (m) {
                int idx = pos + __popc(mask & ((1u << lane) - 1));
                int s = ssrc[e];
                g_edge[gb + idx] = make_int2(s, __float_as_int(dinv[s] * dd));
            }
            pos += __popc(mask);
        }
    }
}

// ---------------- kernel 2: tensor-core 3xTF32 GEMM -------------------------
// C[M,128] = H[M,K] @ W[K,128]; LAYER0: H = [ztab[z]|x] (K=256)
// k8-sliced, double-buffered SMEM; A stride 12, B stride 136 (conflict-free).
#define AS 12
#define BS 136
#define A_BUF (128 * AS)   // 1536 floats
#define B_BUF (8 * BS)     // 1088 floats
#define GEMM_SMEM ((2 * 2 * A_BUF + 2 * 2 * B_BUF) * 4)  // 41984 B

template <int LAYER0, int K>
__global__ void __launch_bounds__(256, 2) gemm_tc(
    const float* __restrict__ A_in, const int* __restrict__ z,
    const float* __restrict__ ztab, const float* __restrict__ xin,
    const float* __restrict__ W,    float* __restrict__ C, int M)
{
    extern __shared__ float sm[];
    // layout: Ah[2][A_BUF], Al[2][A_BUF], Bh[2][B_BUF], Bl[2][B_BUF]
    float* AH = sm;
    float* AL = AH + 2 * A_BUF;
    float* BH = AL + 2 * A_BUF;
    float* BL = BH + 2 * B_BUF;

    const int tid = threadIdx.x;
    const int lane = tid & 31, wid = tid >> 5;
    const int wm = wid & 1, wn = wid >> 1;      // 2 x 4 warp grid
    const int l4 = lane >> 2, lm = lane & 3;
    const int row0 = blockIdx.x * 128;

    // --- staging thread geometry ---
    const int st_row = tid >> 1;                 // A: 0..127
    const int st_c0  = (tid & 1) * 4;
    const int st_bk  = tid >> 5;                 // B: k row 0..7
    const int st_bn  = (tid & 31) * 4;

    const int gr  = row0 + st_row;
    const int grc = gr < M ? gr : (M - 1);
    const float* pz = nullptr;
    const float* px = nullptr;
    const float* pa = nullptr;
    if (LAYER0) {
        pz = ztab + (size_t)z[grc] * HID;
        px = xin + (size_t)grc * HID;
    } else {
        pa = A_in + (size_t)grc * K;
    }

    const int S = K / 8;

    auto stage = [&](int s, int p) {
        // A slice [128 x 8]
        int kk = s * 8 + st_c0;
        float4 v;
        if (LAYER0)
            v = (kk < 128) ? *(const float4*)(pz + kk)
                           : *(const float4*)(px + kk - 128);
        else
            v = *(const float4*)(pa + kk);
        float4 h, l;
        h.x = f2tf32f(v.x); l.x = v.x - h.x;
        h.y = f2tf32f(v.y); l.y = v.y - h.y;
        h.z = f2tf32f(v.z); l.z = v.z - h.z;
        h.w = f2tf32f(v.w); l.w = v.w - h.w;
        *(float4*)&AH[p * A_BUF + st_row * AS + st_c0] = h;
        *(float4*)&AL[p * A_BUF + st_row * AS + st_c0] = l;
        // B slice [8 x 128]
        float4 w4 = *(const float4*)(W + (size_t)(s * 8 + st_bk) * HID + st_bn);
        float4 wh, wl;
        wh.x = f2tf32f(w4.x); wl.x = w4.x - wh.x;
        wh.y = f2tf32f(w4.y); wl.y = w4.y - wh.y;
        wh.z = f2tf32f(w4.z); wl.z = w4.z - wh.z;
        wh.w = f2tf32f(w4.w); wl.w = w4.w - wh.w;
        *(float4*)&BH[p * B_BUF + st_bk * BS + st_bn] = wh;
        *(float4*)&BL[p * B_BUF + st_bk * BS + st_bn] = wl;
    };

    float acc[4][4][4];
#pragma unroll
    for (int mi = 0; mi < 4; mi++)
#pragma unroll
        for (int nj = 0; nj < 4; nj++)
#pragma unroll
            for (int q = 0; q < 4; q++) acc[mi][nj][q] = 0.f;

    stage(0, 0);

#pragma unroll 1
    for (int s = 0; s < S; s++) {
        __syncthreads();
        if (s + 1 < S) stage(s + 1, (s + 1) & 1);

        const int p = s & 1;
        const float* ah = AH + p * A_BUF;
        const float* al = AL + p * A_BUF;
        const float* bh = BH + p * B_BUF;
        const float* bl = BL + p * B_BUF;

        uint32_t a_h[4][4], a_l[4][4];
#pragma unroll
        for (int mi = 0; mi < 4; mi++) {
            int r = wm * 64 + mi * 16 + l4;
            a_h[mi][0] = __float_as_uint(ah[r * AS + lm]);
            a_h[mi][1] = __float_as_uint(ah[(r + 8) * AS + lm]);
            a_h[mi][2] = __float_as_uint(ah[r * AS + lm + 4]);
            a_h[mi][3] = __float_as_uint(ah[(r + 8) * AS + lm + 4]);
            a_l[mi][0] = __float_as_uint(al[r * AS + lm]);
            a_l[mi][1] = __float_as_uint(al[(r + 8) * AS + lm]);
            a_l[mi][2] = __float_as_uint(al[r * AS + lm + 4]);
            a_l[mi][3] = __float_as_uint(al[(r + 8) * AS + lm + 4]);
        }
#pragma unroll
        for (int nj = 0; nj < 4; nj++) {
            int n = wn * 32 + nj * 8 + l4;
            uint32_t bh0 = __float_as_uint(bh[lm * BS + n]);
            uint32_t bh1 = __float_as_uint(bh[(lm + 4) * BS + n]);
            uint32_t bl0 = __float_as_uint(bl[lm * BS + n]);
            uint32_t bl1 = __float_as_uint(bl[(lm + 4) * BS + n]);
#pragma unroll
            for (int mi = 0; mi < 4; mi++) {
                mma_tf32(acc[mi][nj], a_h[mi], bh0, bh1);
                mma_tf32(acc[mi][nj], a_h[mi], bl0, bl1);
                mma_tf32(acc[mi][nj], a_l[mi], bh0, bh1);
            }
        }
    }

    // ---- epilogue: direct stores -------------------------------------------
#pragma unroll
    for (int mi = 0; mi < 4; mi++) {
#pragma unroll
        for (int nj = 0; nj < 4; nj++) {
            int r = row0 + wm * 64 + mi * 16 + l4;
            int c = wn * 32 + nj * 8 + 2 * lm;
            if (r < M)
                *(float2*)(C + (size_t)r * HID + c) =
                    make_float2(acc[mi][nj][0], acc[mi][nj][1]);
            if (r + 8 < M)
                *(float2*)(C + (size_t)(r + 8) * HID + c) =
                    make_float2(acc[mi][nj][2], acc[mi][nj][3]);
        }
    }
}

// ---------------- kernel 3: X = tanh(A_norm @ T + b) per graph --------------
__global__ void __launch_bounds__(256) agg_tanh(
    const float* __restrict__ T, const float* __restrict__ bias,
    float* __restrict__ Xout)
{
    extern __shared__ float Ts[]; // [100][128]
    const int g = blockIdx.x, tid = threadIdx.x;
    const float* Tg = T + (size_t)g * NODES * HID;

    for (int t = tid; t < NODES * HID / 4; t += 256)
        ((float4*)Ts)[t] = ((const float4*)Tg)[t];
    __syncthreads();

    const int lane = tid & 31, warp = tid >> 5;
    const float4 bv = *(const float4*)(bias + lane * 4);
    const int2* ep  = g_edge + (size_t)g * EDGES;
    const int*  offp = g_off + g * 101;

    for (int d = warp; d < NODES; d += 8) {
        int e0 = offp[d], e1 = offp[d + 1];
        float4 a4 = make_float4(0.f, 0.f, 0.f, 0.f);
        for (int e = e0; e < e1; e++) {
            int2 pe = ep[e];
            float w = __int_as_float(pe.y);
            float4 tv = *(const float4*)&Ts[pe.x * HID + lane * 4];
            a4.x += w * tv.x; a4.y += w * tv.y;
            a4.z += w * tv.z; a4.w += w * tv.w;
        }
        float4 o;
        o.x = acc_tanh(a4.x + bv.x);
        o.y = acc_tanh(a4.y + bv.y);
        o.z = acc_tanh(a4.z + bv.z);
        o.w = acc_tanh(a4.w + bv.w);
        *(float4*)(Xout + ((size_t)g * NODES + d) * HID + lane * 4) = o;
    }
}

// ---------------- final: layer3 + sort-pool + conv + MLP --------------------
#define FINAL_SMEM_FLOATS 39028
__global__ void __launch_bounds__(256) final_k(
    const float* __restrict__ W3,  const float* __restrict__ b3,
    const float* __restrict__ cw1, const float* __restrict__ cb1,
    const float* __restrict__ cw2, const float* __restrict__ cb2,
    const float* __restrict__ mW1, const float* __restrict__ mb1,
    const float* __restrict__ mW2, const float* __restrict__ mb2,
    float* __restrict__ out)
{
    extern __shared__ float sm[];
    float* X2s  = sm;                  // 100*129
    float* cw1s = X2s + 100 * 129;     // 16*388 = 6208
    float* feat = cw1s + 6208;         // 40*388 = 15520
    float* cw2s = feat + 15520;        // 2560
    float* t3   = cw2s + 2560;         // 100
    float* x3   = t3 + 100;            // 100
    float* y1   = x3 + 100;            // 640
    float* mmp  = y1 + 640;            // 320
    float* flat = mmp + 320;           // 512
    float* rr   = flat + 512;          // 128
    int*   topi = (int*)(rr + 128);    // 40

    const int g = blockIdx.x, tid = threadIdx.x;
    const float* X2g = g_X2 + (size_t)g * NODES * HID;

    for (int t = tid; t < NODES * HID; t += 256) {
        int i = t >> 7, d = t & 127;
        X2s[i * 129 + d] = X2g[t];
    }
    for (int t = tid; t < 16 * 385; t += 256) {
        int c = t / 385, d = t - c * 385;
        cw1s[c * 388 + d] = cw1[t];
    }
    if (tid < 16) {
        cw1s[tid * 388 + 385] = 0.f;
        cw1s[tid * 388 + 386] = 0.f;
        cw1s[tid * 388 + 387] = 0.f;
    }
    for (int t = tid; t < 2560; t += 256) cw2s[t] = cw2[t];
    __syncthreads();

    if (tid < NODES) {
        float a = 0.f;
#pragma unroll 8
        for (int k = 0; k < HID; k++) a += X2s[tid * 129 + k] * W3[k];
        t3[tid] = a;
    }
    __syncthreads();

    if (tid < NODES) {
        const int*  offp = g_off + g * 101;
        const int2* ep   = g_edge + (size_t)g * EDGES;
        float a = 0.f;
        int e1 = offp[tid + 1];
        for (int e = offp[tid]; e < e1; e++) {
            int2 pe = ep[e];
            a += __int_as_float(pe.y) * t3[pe.x];
        }
        x3[tid] = acc_tanh(a + b3[0]);
    }
    __syncthreads();

    if (tid < NODES) {
        float v = x3[tid];
        int r = 0;
        for (int j = 0; j < NODES; j++) {
            float u = x3[j];
            r += (u > v) || (u == v && j < tid);
        }
        if (r < KTOP) topi[r] = tid;
    }
    __syncthreads();

    for (int t = tid; t < KTOP * HID; t += 256) {
        int k = t >> 7, d = t & 127;
        int node = topi[k];
        size_t gbase = ((size_t)g * NODES + node) * HID;
        feat[k * 388 + d]       = g_X0[gbase + d];
        feat[k * 388 + 128 + d] = g_X1[gbase + d];
        feat[k * 388 + 256 + d] = X2s[node * 129 + d];
    }
    if (tid < KTOP) {
        feat[tid * 388 + 384] = x3[topi[tid]];
        feat[tid * 388 + 385] = 0.f;
        feat[tid * 388 + 386] = 0.f;
        feat[tid * 388 + 387] = 0.f;
    }
    __syncthreads();

    for (int o = tid; o < 640; o += 256) {
        int c = o & 15, kp = o >> 4;
        float a = cb1[c];
        const float4* wr = (const float4*)(cw1s + c * 388);
        const float4* fr = (const float4*)(feat + kp * 388);
#pragma unroll 4
        for (int d = 0; d < 97; d++) {
            float4 w4 = wr[d], f4 = fr[d];
            a += w4.x * f4.x + w4.y * f4.y + w4.z * f4.z + w4.w * f4.w;
        }
        y1[c * 40 + kp] = fmaxf(a, 0.f);
    }
    __syncthreads();

    for (int t = tid; t < 320; t += 256) {
        int c = t / 20, p = t % 20;
        mmp[t] = fmaxf(y1[c * 40 + 2 * p], y1[c * 40 + 2 * p + 1]);
    }
    __syncthreads();

    for (int t = tid; t < 512; t += 256) {
        int o2 = t >> 4, p = t & 15;
        float a = cb2[o2];
#pragma unroll
        for (int c = 0; c < 16; c++)
#pragma unroll
            for (int u = 0; u < 5; u++)
                a += cw2s[(o2 * 16 + c) * 5 + u] * mmp[c * 20 + p + u];
        flat[t] = fmaxf(a, 0.f);
    }
    __syncthreads();

    {
        int col = tid & 127, half = tid >> 7;
        float a = 0.f;
        const float* fp = flat + half * 256;
        const float* wp = mW1 + (size_t)(half * 256) * 128 + col;
#pragma unroll 8
        for (int i = 0; i < 256; i++) a += fp[i] * wp[(size_t)i * 128];
        y1[tid] = a;
    }
    __syncthreads();
    if (tid < 128) rr[tid] = fmaxf(y1[tid] + y1[tid + 128] + mb1[tid], 0.f);
    __syncthreads();

    if (tid < 32) {
        float s = 0.f;
#pragma unroll
        for (int q = 0; q < 4; q++) s += rr[tid + 32 * q] * mW2[tid + 32 * q];
        for (int off2 = 16; off2 > 0; off2 >>= 1)
            s += __shfl_down_sync(0xffffffffu, s, off2);
        if (tid == 0) out[g] = s + mb2[0];
    }
}

// ---------------- host ------------------------------------------------------
extern "C" void kernel_launch(void* const* d_in, const int* in_sizes, int n_in,
                              void* d_out, int out_size)
{
    const float* x    = (const float*)d_in[0];
    const int*   z    = (const int*)  d_in[1];
    const int*   ei   = (const int*)  d_in[2];
    const float* ztab = (const float*)d_in[4];
    const float* W0   = (const float*)d_in[5];
    const float* b0   = (const float*)d_in[6];
    const float* W1   = (const float*)d_in[7];
    const float* b1   = (const float*)d_in[8];
    const float* W2   = (const float*)d_in[9];
    const float* b2   = (const float*)d_in[10];
    const float* W3   = (const float*)d_in[11];
    const float* b3   = (const float*)d_in[12];
    const float* cw1  = (const float*)d_in[13];
    const float* cb1  = (const float*)d_in[14];
    const float* cw2  = (const float*)d_in[15];
    const float* cb2  = (const float*)d_in[16];
    const float* mW1  = (const float*)d_in[17];
    const float* mb1  = (const float*)d_in[18];
    const float* mW2  = (const float*)d_in[19];
    const float* mb2  = (const float*)d_in[20];
    float* out = (float*)d_out;

    float *T, *X0, *X1, *X2;
    cudaGetSymbolAddress((void**)&T,  g_T);
    cudaGetSymbolAddress((void**)&X0, g_X0);
    cudaGetSymbolAddress((void**)&X1, g_X1);
    cudaGetSymbolAddress((void**)&X2, g_X2);

    cudaFuncSetAttribute(agg_tanh, cudaFuncAttributeMaxDynamicSharedMemorySize, 64 * 1024);
    cudaFuncSetAttribute(final_k,  cudaFuncAttributeMaxDynamicSharedMemorySize, 160 * 1024);

    const int GEMM_GRID = (NTOT + 127) / 128;
    const int AGG_SMEM  = NODES * HID * (int)sizeof(float); // 51200

    build_csr<<<NG, 256>>>(ei);

    gemm_tc<1, 256><<<GEMM_GRID, 256, GEMM_SMEM>>>(nullptr, z, ztab, x, W0, T, NTOT);
    agg_tanh<<<NG, 256, AGG_SMEM>>>(T, b0, X0);

    gemm_tc<0, 128><<<GEMM_GRID, 256, GEMM_SMEM>>>(X0, nullptr, nullptr, nullptr, W1, T, NTOT);
    agg_tanh<<<NG, 256, AGG_SMEM>>>(T, b1, X1);

    gemm_tc<0, 128><<<GEMM_GRID, 256, GEMM_SMEM>>>(X1, nullptr, nullptr, nullptr, W2, T, NTOT);
    agg_tanh<<<NG, 256, AGG_SMEM>>>(T, b2, X2);

    final_k<<<NG, 256, FINAL_SMEM_FLOATS * 4>>>(W3, b3, cw1, cb1, cw2, cb2,
                                                mW1, mb1, mW2, mb2, out);
}

// round 5
// speedup vs baseline: 1.1625x; 1.1625x over previous
#include <cuda_runtime.h>
#include <cstdint>

#define NG    1000
#define NODES 100
#define EDGES 1600
#define NTOT  100000
#define ETOT  1600000
#define HID   128
#define KTOP  40

// ---------------- scratch (device globals; no runtime allocation) ----------
__device__ float g_T [(size_t)NTOT * HID];
__device__ float g_X0[(size_t)NTOT * HID];
__device__ float g_X1[(size_t)NTOT * HID];
__device__ float g_X2[(size_t)NTOT * HID];
__device__ int   g_off [NG * 101];
__device__ float g_dinv[NTOT];
__device__ int2  g_edge[ETOT];   // (src, bitcast norm)

// ---------------- helpers ---------------------------------------------------
__device__ __forceinline__ float acc_tanh(float x) {
    float xc = fminf(fmaxf(x, -10.f), 10.f);
    float e  = __expf(2.f * xc);
    return (e - 1.f) / (e + 1.f);
}
__device__ __forceinline__ float f2tf32f(float x) {
    uint32_t r;
    asm("cvt.rna.tf32.f32 %0, %1;" : "=r"(r) : "f"(x));
    return __uint_as_float(r);
}
__device__ __forceinline__ void mma_tf32(float c[4], const uint32_t a[4],
                                         const uint32_t b0, const uint32_t b1) {
    asm volatile(
        "mma.sync.aligned.m16n8k8.row.col.f32.tf32.tf32.f32 "
        "{%0,%1,%2,%3}, {%4,%5,%6,%7}, {%8,%9}, {%0,%1,%2,%3};\n"
        : "+f"(c[0]), "+f"(c[1]), "+f"(c[2]), "+f"(c[3])
        : "r"(a[0]), "r"(a[1]), "r"(a[2]), "r"(a[3]), "r"(b0), "r"(b1));
}
__device__ __forceinline__ uint32_t smem_u32(const void* p) {
    return (uint32_t)__cvta_generic_to_shared(p);
}
#define CP16(dst, src) \
    asm volatile("cp.async.cg.shared.global [%0], [%1], 16;\n" :: "r"(dst), "l"(src))
#define CPCOMMIT() asm volatile("cp.async.commit_group;\n" ::: "memory")
#define CPWAIT2()  asm volatile("cp.async.wait_group 2;\n" ::: "memory")

__device__ __forceinline__ unsigned long long pkf2(float a, float b) {
    unsigned long long r;
    asm("mov.b64 %0, {%1, %2};" : "=l"(r) : "r"(__float_as_int(a)), "r"(__float_as_int(b)));
    return r;
}
__device__ __forceinline__ void ffma2(unsigned long long& d,
                                      unsigned long long a, unsigned long long b) {
    asm("fma.rn.f32x2 %0, %1, %2, %3;" : "=l"(d) : "l"(a), "l"(b), "l"(d));
}
__device__ __forceinline__ float hsum2(unsigned long long u) {
    int lo, hi;
    asm("mov.b64 {%0, %1}, %2;" : "=r"(lo), "=r"(hi) : "l"(u));
    return __int_as_float(lo) + __int_as_float(hi);
}

// ---------------- csr part 1: degrees, dinv, offsets ------------------------
__global__ void __launch_bounds__(256) csr_deg(const int* __restrict__ ei)
{
    __shared__ int deg[NODES];
    const int g = blockIdx.x, tid = threadIdx.x;
    const int base = g * NODES;
    const int* dste = ei + (size_t)ETOT + (size_t)g * EDGES;

    if (tid < NODES) deg[tid] = 0;
    __syncthreads();
    for (int e = tid; e < EDGES; e += 256)
        atomicAdd(&deg[dste[e] - base], 1);
    __syncthreads();

    if (tid < NODES)
        g_dinv[base + tid] = deg[tid] > 0 ? rsqrtf((float)deg[tid]) : 0.f;
    if (tid == 0) {
        int acc = 0;
        for (int i = 0; i < NODES; i++) { g_off[g * 101 + i] = acc; acc += deg[i]; }
        g_off[g * 101 + NODES] = acc;
    }
}

// ---------------- csr part 2: deterministic ordered fill --------------------
__global__ void __launch_bounds__(256) csr_fill(const int* __restrict__ ei)
{
    __shared__ int   sdst[EDGES];
    __shared__ int   ssrc[EDGES];
    __shared__ float dinv[NODES];
    __shared__ int   offs[NODES + 1];

    const int g = blockIdx.x, tid = threadIdx.x;
    const int base = g * NODES;
    const int* srce = ei + (size_t)g * EDGES;
    const int* dste = ei + (size_t)ETOT + (size_t)g * EDGES;

    for (int e = tid; e < EDGES; e += 256) {
        ssrc[e] = srce[e] - base;
        sdst[e] = dste[e] - base;
    }
    if (tid < NODES) dinv[tid] = g_dinv[base + tid];
    if (tid <= NODES) offs[tid] = g_off[g * 101 + tid];
    __syncthreads();

    const int lane = tid & 31, warp = tid >> 5;
    const size_t gb = (size_t)g * EDGES;
    for (int d = warp; d < NODES; d += 8) {
        int pos = offs[d];
        float dd = dinv[d];
        for (int eb = 0; eb < EDGES; eb += 32) {
            int e = eb + lane;
            bool m = (sdst[e] == d);
            unsigned mask = __ballot_sync(0xffffffffu, m);
            if (m) {
                int idx = pos + __popc(mask & ((1u << lane) - 1));
                int s = ssrc[e];
                g_edge[gb + idx] = make_int2(s, __float_as_int(dinv[s] * dd));
            }
            pos += __popc(mask);
        }
    }
}

// ---------------- tensor-core 3xTF32 GEMM, 4-stage cp.async -----------------
// C[M,128] = H[M,K] @ W[K,128]; LAYER0: H = [ztab[z]|x] (K=256)
#define A_ST 1024            // 128 rows * 8 (stride 8 floats)
#define B_ST 1056            // 8 rows * 132 (stride 132 floats)
#define GEMM_SMEM ((4 * A_ST + 4 * B_ST) * 4)   // 33280 B

template <int LAYER0, int K>
__global__ void __launch_bounds__(256, 2) gemm_tc(
    const float* __restrict__ A_in, const int* __restrict__ z,
    const float* __restrict__ ztab, const float* __restrict__ xin,
    const float* __restrict__ W,    float* __restrict__ C, int M)
{
    extern __shared__ float sm[];
    float* As = sm;              // [4][A_ST]
    float* Bs = sm + 4 * A_ST;   // [4][B_ST]

    const int tid = threadIdx.x;
    const int lane = tid & 31, wid = tid >> 5;
    const int wm = wid & 1, wn = wid >> 1;      // 2 x 4 warp grid
    const int l4 = lane >> 2, lm = lane & 3;
    const int row0 = blockIdx.x * 128;

    // staging geometry: each thread issues 1 A-chunk + 1 B-chunk per slice
    const int arow = tid >> 1, ahalf = (tid & 1) * 4;
    const int bk = tid >> 5, bn4 = (tid & 31) * 4;

    const int gr = row0 + arow;
    const int grc = gr < M ? gr : (M - 1);
    const float* aptr0;
    const float* aptr1 = nullptr;
    if (LAYER0) {
        aptr0 = ztab + (size_t)z[grc] * HID;
        aptr1 = xin + (size_t)grc * HID;
    } else {
        aptr0 = A_in + (size_t)grc * K;
    }
    const float* bptr = W + (size_t)bk * HID + bn4;
    const uint32_t adst = smem_u32(As + arow * 8 + ahalf);
    const uint32_t bdst = smem_u32(Bs + bk * 132 + bn4);

    const int S = K / 8;

    auto issue = [&](int s) {
        const int buf = s & 3;
        const int kk = s * 8 + ahalf;
        const float* asrc;
        if (LAYER0)
            asrc = (kk < 128) ? (aptr0 + kk) : (aptr1 + kk - 128);
        else
            asrc = aptr0 + kk;
        CP16(adst + buf * (A_ST * 4), asrc);
        CP16(bdst + buf * (B_ST * 4), bptr + (size_t)s * 8 * HID);
        CPCOMMIT();
    };

    float acc[4][4][4];
#pragma unroll
    for (int mi = 0; mi < 4; mi++)
#pragma unroll
        for (int nj = 0; nj < 4; nj++)
#pragma unroll
            for (int q = 0; q < 4; q++) acc[mi][nj][q] = 0.f;

    issue(0); issue(1); issue(2);

#pragma unroll 1
    for (int s = 0; s < S; s++) {
        CPWAIT2();
        __syncthreads();
        if (s + 3 < S) issue(s + 3);

        const float* A0 = As + (s & 3) * A_ST;
        const float* B0 = Bs + (s & 3) * B_ST;

        // B fragments: hi/lo split in registers
        uint32_t bh[4][2], bl[4][2];
#pragma unroll
        for (int nj = 0; nj < 4; nj++) {
            int n = wn * 32 + nj * 8 + l4;
            float r0 = B0[lm * 132 + n];
            float r1 = B0[(lm + 4) * 132 + n];
            float h0 = f2tf32f(r0), h1 = f2tf32f(r1);
            bh[nj][0] = __float_as_uint(h0);
            bh[nj][1] = __float_as_uint(h1);
            bl[nj][0] = __float_as_uint(r0 - h0);
            bl[nj][1] = __float_as_uint(r1 - h1);
        }
#pragma unroll
        for (int mi = 0; mi < 4; mi++) {
            int r = (wm * 4 + mi) * 16 + l4;
            float r0 = A0[r * 8 + lm];
            float r1 = A0[(r + 8) * 8 + lm];
            float r2 = A0[r * 8 + lm + 4];
            float r3 = A0[(r + 8) * 8 + lm + 4];
            float h0 = f2tf32f(r0), h1 = f2tf32f(r1);
            float h2 = f2tf32f(r2), h3 = f2tf32f(r3);
            uint32_t ah[4] = { __float_as_uint(h0), __float_as_uint(h1),
                               __float_as_uint(h2), __float_as_uint(h3) };
            uint32_t al[4] = { __float_as_uint(r0 - h0), __float_as_uint(r1 - h1),
                               __float_as_uint(r2 - h2), __float_as_uint(r3 - h3) };
#pragma unroll
            for (int nj = 0; nj < 4; nj++) {
                mma_tf32(acc[mi][nj], ah, bh[nj][0], bh[nj][1]);
                mma_tf32(acc[mi][nj], ah, bl[nj][0], bl[nj][1]);
                mma_tf32(acc[mi][nj], al, bh[nj][0], bh[nj][1]);
            }
        }
    }

    // ---- epilogue: direct stores -------------------------------------------
#pragma unroll
    for (int mi = 0; mi < 4; mi++) {
#pragma unroll
        for (int nj = 0; nj < 4; nj++) {
            int r = row0 + wm * 64 + mi * 16 + l4;
            int c = wn * 32 + nj * 8 + 2 * lm;
            if (r < M)
                *(float2*)(C + (size_t)r * HID + c) =
                    make_float2(acc[mi][nj][0], acc[mi][nj][1]);
            if (r + 8 < M)
                *(float2*)(C + (size_t)(r + 8) * HID + c) =
                    make_float2(acc[mi][nj][2], acc[mi][nj][3]);
        }
    }
}

// ---------------- X = tanh(A_norm @ T + b) per graph ------------------------
__global__ void __launch_bounds__(256) agg_tanh(
    const float* __restrict__ T, const float* __restrict__ bias,
    float* __restrict__ Xout)
{
    extern __shared__ float Ts[]; // [100][128]
    const int g = blockIdx.x, tid = threadIdx.x;
    const float* Tg = T + (size_t)g * NODES * HID;

    for (int t = tid; t < NODES * HID / 4; t += 256)
        ((float4*)Ts)[t] = ((const float4*)Tg)[t];
    __syncthreads();

    const int lane = tid & 31, warp = tid >> 5;
    const float4 bv = *(const float4*)(bias + lane * 4);
    const int2* ep  = g_edge + (size_t)g * EDGES;
    const int*  offp = g_off + g * 101;

    for (int d = warp; d < NODES; d += 8) {
        int e0 = offp[d], e1 = offp[d + 1];
        float4 a4 = make_float4(0.f, 0.f, 0.f, 0.f);
        for (int e = e0; e < e1; e++) {
            int2 pe = ep[e];
            float w = __int_as_float(pe.y);
            float4 tv = *(const float4*)&Ts[pe.x * HID + lane * 4];
            a4.x += w * tv.x; a4.y += w * tv.y;
            a4.z += w * tv.z; a4.w += w * tv.w;
        }
        float4 o;
        o.x = acc_tanh(a4.x + bv.x);
        o.y = acc_tanh(a4.y + bv.y);
        o.z = acc_tanh(a4.z + bv.z);
        o.w = acc_tanh(a4.w + bv.w);
        *(float4*)(Xout + ((size_t)g * NODES + d) * HID + lane * 4) = o;
    }
}

// ---------------- final: layer3 + sort-pool + conv + MLP --------------------
#define FINAL_SMEM_FLOATS 26256
__global__ void __launch_bounds__(256) final_k(
    const float* __restrict__ W3,  const float* __restrict__ b3,
    const float* __restrict__ cw1, const float* __restrict__ cb1,
    const float* __restrict__ cw2, const float* __restrict__ cb2,
    const float* __restrict__ mW1, const float* __restrict__ mb1,
    const float* __restrict__ mW2, const float* __restrict__ mb2,
    float* __restrict__ out)
{
    extern __shared__ float sm[];
    float* W3s  = sm;                  // 128
    float* cw1s = W3s + 128;           // 16*388 = 6208
    float* cw2s = cw1s + 6208;         // 2560
    float* feat = cw2s + 2560;         // 40*388 = 15520
    float* t3   = feat + 15520;        // 100
    float* x3   = t3 + 100;            // 100
    float* y1   = x3 + 100;            // 640
    float* mmp  = y1 + 640;            // 320
    float* flat = mmp + 320;           // 512
    float* rr   = flat + 512;          // 128
    int*   topi = (int*)(rr + 128);    // 40

    const int g = blockIdx.x, tid = threadIdx.x;
    const float* X2g = g_X2 + (size_t)g * NODES * HID;

    if (tid < 128) W3s[tid] = W3[tid];
    for (int t = tid; t < 16 * 385; t += 256) {
        int c = t / 385, d = t - c * 385;
        cw1s[c * 388 + d] = cw1[t];
    }
    if (tid < 16) {
        cw1s[tid * 388 + 385] = 0.f;
        cw1s[tid * 388 + 386] = 0.f;
        cw1s[tid * 388 + 387] = 0.f;
    }
    for (int t = tid; t < 2560; t += 256) cw2s[t] = cw2[t];
    __syncthreads();

    // ---- layer 3: t3 = X2 @ W3 (X2 read from L2) -----------------------------
    if (tid < NODES) {
        const float4* xr = (const float4*)(X2g + (size_t)tid * HID);
        const float4* wr = (const float4*)W3s;
        float a = 0.f;
#pragma unroll 8
        for (int k = 0; k < 32; k++) {
            float4 xv = xr[k], wv = wr[k];
            a += xv.x * wv.x + xv.y * wv.y + xv.z * wv.z + xv.w * wv.w;
        }
        t3[tid] = a;
    }
    __syncthreads();

    if (tid < NODES) {
        const int*  offp = g_off + g * 101;
        const int2* ep   = g_edge + (size_t)g * EDGES;
        float a = 0.f;
        int e1 = offp[tid + 1];
        for (int e = offp[tid]; e < e1; e++) {
            int2 pe = ep[e];
            a += __int_as_float(pe.y) * t3[pe.x];
        }
        x3[tid] = acc_tanh(a + b3[0]);
    }
    __syncthreads();

    // ---- stable descending rank --------------------------------------------
    if (tid < NODES) {
        float v = x3[tid];
        int r = 0;
        for (int j = 0; j < NODES; j++) {
            float u = x3[j];
            r += (u > v) || (u == v && j < tid);
        }
        if (r < KTOP) topi[r] = tid;
    }
    __syncthreads();

    // ---- gather feat rows of top-K nodes (from L2) ---------------------------
    for (int t = tid; t < KTOP * HID; t += 256) {
        int k = t >> 7, d = t & 127;
        int node = topi[k];
        size_t gbase = ((size_t)g * NODES + node) * HID;
        feat[k * 388 + d]       = g_X0[gbase + d];
        feat[k * 388 + 128 + d] = g_X1[gbase + d];
        feat[k * 388 + 256 + d] = g_X2[gbase + d];
    }
    if (tid < KTOP) {
        feat[tid * 388 + 384] = x3[topi[tid]];
        feat[tid * 388 + 385] = 0.f;
        feat[tid * 388 + 386] = 0.f;
        feat[tid * 388 + 387] = 0.f;
    }
    __syncthreads();

    // ---- conv1 + relu (packed f32x2 FMA over padded 388) ---------------------
    for (int o = tid; o < 640; o += 256) {
        int c = o & 15, kp = o >> 4;
        const float4* wr = (const float4*)(cw1s + c * 388);
        const float4* fr = (const float4*)(feat + kp * 388);
        unsigned long long s0 = 0ull, s1 = 0ull;
#pragma unroll 4
        for (int d = 0; d < 97; d++) {
            float4 w4 = wr[d], f4 = fr[d];
            ffma2(s0, pkf2(w4.x, w4.y), pkf2(f4.x, f4.y));
            ffma2(s1, pkf2(w4.z, w4.w), pkf2(f4.z, f4.w));
        }
        float a = cb1[c] + hsum2(s0) + hsum2(s1);
        y1[c * 40 + kp] = fmaxf(a, 0.f);
    }
    __syncthreads();

    // ---- maxpool(2,2) -------------------------------------------------------
    for (int t = tid; t < 320; t += 256) {
        int c = t / 20, p = t % 20;
        mmp[t] = fmaxf(y1[c * 40 + 2 * p], y1[c * 40 + 2 * p + 1]);
    }
    __syncthreads();

    // ---- conv2 (16->32, k=5) + relu -----------------------------------------
    for (int t = tid; t < 512; t += 256) {
        int o2 = t >> 4, p = t & 15;
        float a = cb2[o2];
#pragma unroll
        for (int c = 0; c < 16; c++)
#pragma unroll
            for (int u = 0; u < 5; u++)
                a += cw2s[(o2 * 16 + c) * 5 + u] * mmp[c * 20 + p + u];
        flat[t] = fmaxf(a, 0.f);
    }
    __syncthreads();

    // ---- mlp1 (split-K over 2 thread groups) --------------------------------
    {
        int col = tid & 127, half = tid >> 7;
        float a = 0.f;
        const float* fp = flat + half * 256;
        const float* wp = mW1 + (size_t)(half * 256) * 128 + col;
#pragma unroll 8
        for (int i = 0; i < 256; i++) a += fp[i] * wp[(size_t)i * 128];
        y1[tid] = a;
    }
    __syncthreads();
    if (tid < 128) rr[tid] = fmaxf(y1[tid] + y1[tid + 128] + mb1[tid], 0.f);
    __syncthreads();

    // ---- mlp2 + write -------------------------------------------------------
    if (tid < 32) {
        float s = 0.f;
#pragma unroll
        for (int q = 0; q < 4; q++) s += rr[tid + 32 * q] * mW2[tid + 32 * q];
        for (int off2 = 16; off2 > 0; off2 >>= 1)
            s += __shfl_down_sync(0xffffffffu, s, off2);
        if (tid == 0) out[g] = s + mb2[0];
    }
}

// ---------------- host ------------------------------------------------------
extern "C" void kernel_launch(void* const* d_in, const int* in_sizes, int n_in,
                              void* d_out, int out_size)
{
    const float* x    = (const float*)d_in[0];
    const int*   z    = (const int*)  d_in[1];
    const int*   ei   = (const int*)  d_in[2];
    const float* ztab = (const float*)d_in[4];
    const float* W0   = (const float*)d_in[5];
    const float* b0   = (const float*)d_in[6];
    const float* W1   = (const float*)d_in[7];
    const float* b1   = (const float*)d_in[8];
    const float* W2   = (const float*)d_in[9];
    const float* b2   = (const float*)d_in[10];
    const float* W3   = (const float*)d_in[11];
    const float* b3   = (const float*)d_in[12];
    const float* cw1  = (const float*)d_in[13];
    const float* cb1  = (const float*)d_in[14];
    const float* cw2  = (const float*)d_in[15];
    const float* cb2  = (const float*)d_in[16];
    const float* mW1  = (const float*)d_in[17];
    const float* mb1  = (const float*)d_in[18];
    const float* mW2  = (const float*)d_in[19];
    const float* mb2  = (const float*)d_in[20];
    float* out = (float*)d_out;

    float *T, *X0, *X1, *X2;
    cudaGetSymbolAddress((void**)&T,  g_T);
    cudaGetSymbolAddress((void**)&X0, g_X0);
    cudaGetSymbolAddress((void**)&X1, g_X1);
    cudaGetSymbolAddress((void**)&X2, g_X2);

    cudaFuncSetAttribute(agg_tanh, cudaFuncAttributeMaxDynamicSharedMemorySize, 64 * 1024);
    cudaFuncSetAttribute(final_k,  cudaFuncAttributeMaxDynamicSharedMemorySize, 120 * 1024);

    const int GEMM_GRID = (NTOT + 127) / 128;
    const int AGG_SMEM  = NODES * HID * (int)sizeof(float); // 51200

    csr_deg <<<NG, 256>>>(ei);   // launch 1
    csr_fill<<<NG, 256>>>(ei);   // launch 2

    gemm_tc<1, 256><<<GEMM_GRID, 256, GEMM_SMEM>>>(nullptr, z, ztab, x, W0, T, NTOT); // 3
    agg_tanh<<<NG, 256, AGG_SMEM>>>(T, b0, X0);                                       // 4

    gemm_tc<0, 128><<<GEMM_GRID, 256, GEMM_SMEM>>>(X0, nullptr, nullptr, nullptr, W1, T, NTOT); // 5
    agg_tanh<<<NG, 256, AGG_SMEM>>>(T, b1, X1);                                       // 6 (ncu capture)

    gemm_tc<0, 128><<<GEMM_GRID, 256, GEMM_SMEM>>>(X1, nullptr, nullptr, nullptr, W2, T, NTOT); // 7
    agg_tanh<<<NG, 256, AGG_SMEM>>>(T, b2, X2);                                       // 8

    final_k<<<NG, 256, FINAL_SMEM_FLOATS * 4>>>(W3, b3, cw1, cb1, cw2, cb2,
                                                mW1, mb1, mW2, mb2, out);             // 9
}

// round 6
// speedup vs baseline: 1.4412x; 1.2398x over previous
#include <cuda_runtime.h>
#include <cstdint>

#define NG    1000
#define NODES 100
#define EDGES 1600
#define NTOT  100000
#define ETOT  1600000
#define HID   128
#define KTOP  40

// ---------------- scratch (device globals; no runtime allocation) ----------
__device__ float g_T [(size_t)NTOT * HID];
__device__ float g_X0[(size_t)NTOT * HID];
__device__ float g_X1[(size_t)NTOT * HID];
__device__ float g_X2[(size_t)NTOT * HID];
__device__ int   g_off [NG * 101];
__device__ int2  g_edge[ETOT];   // (src, bitcast norm)

// ---------------- helpers ---------------------------------------------------
__device__ __forceinline__ float acc_tanh(float x) {
    float xc = fminf(fmaxf(x, -10.f), 10.f);
    float e  = __expf(2.f * xc);
    return (e - 1.f) / (e + 1.f);
}
__device__ __forceinline__ float f2tf32f(float x) {
    uint32_t r;
    asm("cvt.rna.tf32.f32 %0, %1;" : "=r"(r) : "f"(x));
    return __uint_as_float(r);
}
__device__ __forceinline__ void mma_tf32(float c[4], const uint32_t a[4],
                                         const uint32_t b0, const uint32_t b1) {
    asm volatile(
        "mma.sync.aligned.m16n8k8.row.col.f32.tf32.tf32.f32 "
        "{%0,%1,%2,%3}, {%4,%5,%6,%7}, {%8,%9}, {%0,%1,%2,%3};\n"
        : "+f"(c[0]), "+f"(c[1]), "+f"(c[2]), "+f"(c[3])
        : "r"(a[0]), "r"(a[1]), "r"(a[2]), "r"(a[3]), "r"(b0), "r"(b1));
}
__device__ __forceinline__ uint32_t smem_u32(const void* p) {
    return (uint32_t)__cvta_generic_to_shared(p);
}
#define CP16(dst, src) \
    asm volatile("cp.async.cg.shared.global [%0], [%1], 16;\n" :: "r"(dst), "l"(src))
#define CPCOMMIT() asm volatile("cp.async.commit_group;\n" ::: "memory")
#define CPWAIT2()  asm volatile("cp.async.wait_group 2;\n" ::: "memory")

__device__ __forceinline__ unsigned long long pkf2(float a, float b) {
    unsigned long long r;
    asm("mov.b64 %0, {%1, %2};" : "=l"(r) : "r"(__float_as_int(a)), "r"(__float_as_int(b)));
    return r;
}
__device__ __forceinline__ void ffma2(unsigned long long& d,
                                      unsigned long long a, unsigned long long b) {
    asm("fma.rn.f32x2 %0, %1, %2, %3;" : "=l"(d) : "l"(a), "l"(b), "l"(d));
}
__device__ __forceinline__ float hsum2(unsigned long long u) {
    int lo, hi;
    asm("mov.b64 {%0, %1}, %2;" : "=r"(lo), "=r"(hi) : "l"(u));
    return __int_as_float(lo) + __int_as_float(hi);
}

// ---------------- kernel 1: one-pass deterministic CSR ----------------------
// warp-chunk histogram + match_any placement; stable in edge order.
__global__ void __launch_bounds__(256) build_csr(const int* __restrict__ ei)
{
    __shared__ int2  sedge[EDGES];        // local (src,dst)
    __shared__ int   hist [8][104];       // per-chunk dst histogram / run count
    __shared__ int   cbase[8][104];       // per-chunk base offset per dst
    __shared__ int   deg  [NODES];
    __shared__ float dinv [NODES];
    __shared__ int   offs [NODES + 1];

    const int g = blockIdx.x, tid = threadIdx.x;
    const int lane = tid & 31, warp = tid >> 5;
    const int base = g * NODES;
    const int* srce = ei + (size_t)g * EDGES;
    const int* dste = ei + (size_t)ETOT + (size_t)g * EDGES;

    for (int t = tid; t < 8 * 104; t += 256) ((int*)hist)[t] = 0;
    for (int e = tid; e < EDGES; e += 256)
        sedge[e] = make_int2(srce[e] - base, dste[e] - base);
    __syncthreads();

    // phase A: per-warp 200-edge chunk histogram
    const int cbeg = warp * 200;
    for (int j = lane; j < 200; j += 32)
        atomicAdd(&hist[warp][sedge[cbeg + j].y], 1);
    __syncthreads();

    // phase B: degrees, dinv, offsets, chunk bases
    if (tid < NODES) {
        int s = 0;
#pragma unroll
        for (int w = 0; w < 8; w++) s += hist[w][tid];
        deg[tid] = s;
        dinv[tid] = s > 0 ? rsqrtf((float)s) : 0.f;
    }
    __syncthreads();
    if (tid == 0) {
        int acc = 0;
        for (int i = 0; i < NODES; i++) { offs[i] = acc; acc += deg[i]; }
        offs[NODES] = acc;
    }
    __syncthreads();
    if (tid < NODES) {
        int run = offs[tid];
#pragma unroll
        for (int w = 0; w < 8; w++) {
            cbase[w][tid] = run;
            run += hist[w][tid];
            hist[w][tid] = 0;          // reuse as running count
        }
    }
    if (tid <= NODES) g_off[g * 101 + tid] = offs[tid];
    __syncthreads();

    // phase C: stable placement within chunk via match_any rank
    const size_t gb = (size_t)g * EDGES;
    for (int j0 = 0; j0 < 200; j0 += 32) {
        int j = j0 + lane;
        bool act = j < 200;
        unsigned amask = __ballot_sync(0xffffffffu, act);
        if (act) {
            int2 sd = sedge[cbeg + j];
            unsigned mm = __match_any_sync(amask, sd.y);
            unsigned below = mm & ((1u << lane) - 1);
            int c = hist[warp][sd.y];
            __syncwarp(amask);
            g_edge[gb + cbase[warp][sd.y] + c + __popc(below)] =
                make_int2(sd.x, __float_as_int(dinv[sd.x] * dinv[sd.y]));
            if (below == 0)                       // leader lane for this dst
                hist[warp][sd.y] = c + __popc(mm);
        }
        __syncwarp();
    }
}

// ---------------- tensor-core 3xTF32 GEMM, 4-stage cp.async -----------------
#define A_ST 1024            // 128 rows * 8
#define B_ST 1056            // 8 rows * 132
#define GEMM_SMEM ((4 * A_ST + 4 * B_ST) * 4)   // 33280 B

template <int LAYER0, int K>
__global__ void __launch_bounds__(256, 2) gemm_tc(
    const float* __restrict__ A_in, const int* __restrict__ z,
    const float* __restrict__ ztab, const float* __restrict__ xin,
    const float* __restrict__ W,    float* __restrict__ C, int M)
{
    extern __shared__ float sm[];
    float* As = sm;
    float* Bs = sm + 4 * A_ST;

    const int tid = threadIdx.x;
    const int lane = tid & 31, wid = tid >> 5;
    const int wm = wid & 1, wn = wid >> 1;
    const int l4 = lane >> 2, lm = lane & 3;
    const int row0 = blockIdx.x * 128;

    const int arow = tid >> 1, ahalf = (tid & 1) * 4;
    const int bk = tid >> 5, bn4 = (tid & 31) * 4;

    const int gr = row0 + arow;
    const int grc = gr < M ? gr : (M - 1);
    const float* aptr0;
    const float* aptr1 = nullptr;
    if (LAYER0) {
        aptr0 = ztab + (size_t)z[grc] * HID;
        aptr1 = xin + (size_t)grc * HID;
    } else {
        aptr0 = A_in + (size_t)grc * K;
    }
    const float* bptr = W + (size_t)bk * HID + bn4;
    const uint32_t adst = smem_u32(As + arow * 8 + ahalf);
    const uint32_t bdst = smem_u32(Bs + bk * 132 + bn4);

    const int S = K / 8;

    auto issue = [&](int s) {
        const int buf = s & 3;
        const int kk = s * 8 + ahalf;
        const float* asrc;
        if (LAYER0)
            asrc = (kk < 128) ? (aptr0 + kk) : (aptr1 + kk - 128);
        else
            asrc = aptr0 + kk;
        CP16(adst + buf * (A_ST * 4), asrc);
        CP16(bdst + buf * (B_ST * 4), bptr + (size_t)s * 8 * HID);
        CPCOMMIT();
    };

    float acc[4][4][4];
#pragma unroll
    for (int mi = 0; mi < 4; mi++)
#pragma unroll
        for (int nj = 0; nj < 4; nj++)
#pragma unroll
            for (int q = 0; q < 4; q++) acc[mi][nj][q] = 0.f;

    issue(0); issue(1); issue(2);

#pragma unroll 1
    for (int s = 0; s < S; s++) {
        CPWAIT2();
        __syncthreads();
        if (s + 3 < S) issue(s + 3);

        const float* A0 = As + (s & 3) * A_ST;
        const float* B0 = Bs + (s & 3) * B_ST;

        uint32_t bh[4][2], bl[4][2];
#pragma unroll
        for (int nj = 0; nj < 4; nj++) {
            int n = wn * 32 + nj * 8 + l4;
            float r0 = B0[lm * 132 + n];
            float r1 = B0[(lm + 4) * 132 + n];
            float h0 = f2tf32f(r0), h1 = f2tf32f(r1);
            bh[nj][0] = __float_as_uint(h0);
            bh[nj][1] = __float_as_uint(h1);
            bl[nj][0] = __float_as_uint(r0 - h0);
            bl[nj][1] = __float_as_uint(r1 - h1);
        }
#pragma unroll
        for (int mi = 0; mi < 4; mi++) {
            int r = (wm * 4 + mi) * 16 + l4;
            float r0 = A0[r * 8 + lm];
            float r1 = A0[(r + 8) * 8 + lm];
            float r2 = A0[r * 8 + lm + 4];
            float r3 = A0[(r + 8) * 8 + lm + 4];
            float h0 = f2tf32f(r0), h1 = f2tf32f(r1);
            float h2 = f2tf32f(r2), h3 = f2tf32f(r3);
            uint32_t ah[4] = { __float_as_uint(h0), __float_as_uint(h1),
                               __float_as_uint(h2), __float_as_uint(h3) };
            uint32_t al[4] = { __float_as_uint(r0 - h0), __float_as_uint(r1 - h1),
                               __float_as_uint(r2 - h2), __float_as_uint(r3 - h3) };
#pragma unroll
            for (int nj = 0; nj < 4; nj++) {
                mma_tf32(acc[mi][nj], ah, bh[nj][0], bh[nj][1]);
                mma_tf32(acc[mi][nj], ah, bl[nj][0], bl[nj][1]);
                mma_tf32(acc[mi][nj], al, bh[nj][0], bh[nj][1]);
            }
        }
    }

#pragma unroll
    for (int mi = 0; mi < 4; mi++) {
#pragma unroll
        for (int nj = 0; nj < 4; nj++) {
            int r = row0 + wm * 64 + mi * 16 + l4;
            int c = wn * 32 + nj * 8 + 2 * lm;
            if (r < M)
                *(float2*)(C + (size_t)r * HID + c) =
                    make_float2(acc[mi][nj][0], acc[mi][nj][1]);
            if (r + 8 < M)
                *(float2*)(C + (size_t)(r + 8) * HID + c) =
                    make_float2(acc[mi][nj][2], acc[mi][nj][3]);
        }
    }
}

// ---------------- X = tanh(A_norm @ T + b); edges staged in SMEM ------------
#define AGG_SMEM ((NODES * HID + EDGES * 2 + 104) * 4)   // 64416 B
__global__ void __launch_bounds__(512) agg_tanh(
    const float* __restrict__ T, const float* __restrict__ bias,
    float* __restrict__ Xout)
{
    extern __shared__ float sm[];
    float* Ts   = sm;                          // [100][128]
    int2*  sed  = (int2*)(sm + NODES * HID);   // [1600]
    int*   soff = (int*)(sed + EDGES);         // [101]

    const int g = blockIdx.x, tid = threadIdx.x;
    const float* Tg = T + (size_t)g * NODES * HID;

    for (int t = tid; t < NODES * HID / 4; t += 512)
        ((float4*)Ts)[t] = ((const float4*)Tg)[t];
    const int4* egi = (const int4*)(g_edge + (size_t)g * EDGES);
    for (int t = tid; t < EDGES / 2; t += 512)
        ((int4*)sed)[t] = egi[t];
    if (tid <= NODES) soff[tid] = g_off[g * 101 + tid];
    __syncthreads();

    const int lane = tid & 31, warp = tid >> 5;
    const float4 bv = *(const float4*)(bias + lane * 4);

    for (int d = warp; d < NODES; d += 16) {
        int e0 = soff[d], e1 = soff[d + 1];
        float4 acc = make_float4(0.f, 0.f, 0.f, 0.f);
        if (e0 < e1) {
            int2 p0 = sed[e0];
            float4 t0 = *(const float4*)&Ts[p0.x * HID + lane * 4];
#pragma unroll 2
            for (int e = e0 + 1; e < e1; e++) {
                int2 p1 = sed[e];
                float4 t1 = *(const float4*)&Ts[p1.x * HID + lane * 4];
                float w = __int_as_float(p0.y);
                acc.x += w * t0.x; acc.y += w * t0.y;
                acc.z += w * t0.z; acc.w += w * t0.w;
                p0 = p1; t0 = t1;
            }
            float w = __int_as_float(p0.y);
            acc.x += w * t0.x; acc.y += w * t0.y;
            acc.z += w * t0.z; acc.w += w * t0.w;
        }
        float4 o;
        o.x = acc_tanh(acc.x + bv.x);
        o.y = acc_tanh(acc.y + bv.y);
        o.z = acc_tanh(acc.z + bv.z);
        o.w = acc_tanh(acc.w + bv.w);
        *(float4*)(Xout + ((size_t)g * NODES + d) * HID + lane * 4) = o;
    }
}

// ---------------- final: layer3 + sort-pool + conv + MLP --------------------
#define FINAL_SMEM_FLOATS 26256
__global__ void __launch_bounds__(256) final_k(
    const float* __restrict__ W3,  const float* __restrict__ b3,
    const float* __restrict__ cw1, const float* __restrict__ cb1,
    const float* __restrict__ cw2, const float* __restrict__ cb2,
    const float* __restrict__ mW1, const float* __restrict__ mb1,
    const float* __restrict__ mW2, const float* __restrict__ mb2,
    float* __restrict__ out)
{
    extern __shared__ float sm[];
    float* W3s  = sm;                  // 128
    float* cw1s = W3s + 128;           // 16*388 = 6208
    float* cw2s = cw1s + 6208;         // 2560
    float* feat = cw2s + 2560;         // 40*388 = 15520
    float* t3   = feat + 15520;        // 100
    float* x3   = t3 + 100;            // 100
    float* y1   = x3 + 100;            // 640
    float* mmp  = y1 + 640;            // 320
    float* flat = mmp + 320;           // 512
    float* rr   = flat + 512;          // 128
    int*   topi = (int*)(rr + 128);    // 40

    const int g = blockIdx.x, tid = threadIdx.x;
    const float* X2g = g_X2 + (size_t)g * NODES * HID;

    if (tid < 128) W3s[tid] = W3[tid];
    for (int t = tid; t < 16 * 385; t += 256) {
        int c = t / 385, d = t - c * 385;
        cw1s[c * 388 + d] = cw1[t];
    }
    if (tid < 16) {
        cw1s[tid * 388 + 385] = 0.f;
        cw1s[tid * 388 + 386] = 0.f;
        cw1s[tid * 388 + 387] = 0.f;
    }
    for (int t = tid; t < 2560; t += 256) cw2s[t] = cw2[t];
    __syncthreads();

    if (tid < NODES) {
        const float4* xr = (const float4*)(X2g + (size_t)tid * HID);
        const float4* wr = (const float4*)W3s;
        float a = 0.f;
#pragma unroll 8
        for (int k = 0; k < 32; k++) {
            float4 xv = xr[k], wv = wr[k];
            a += xv.x * wv.x + xv.y * wv.y + xv.z * wv.z + xv.w * wv.w;
        }
        t3[tid] = a;
    }
    __syncthreads();

    if (tid < NODES) {
        const int*  offp = g_off + g * 101;
        const int2* ep   = g_edge + (size_t)g * EDGES;
        float a = 0.f;
        int e1 = offp[tid + 1];
        for (int e = offp[tid]; e < e1; e++) {
            int2 pe = ep[e];
            a += __int_as_float(pe.y) * t3[pe.x];
        }
        x3[tid] = acc_tanh(a + b3[0]);
    }
    __syncthreads();

    if (tid < NODES) {
        float v = x3[tid];
        int r = 0;
        for (int j = 0; j < NODES; j++) {
            float u = x3[j];
            r += (u > v) || (u == v && j < tid);
        }
        if (r < KTOP) topi[r] = tid;
    }
    __syncthreads();

    for (int t = tid; t < KTOP * HID; t += 256) {
        int k = t >> 7, d = t & 127;
        int node = topi[k];
        size_t gbase = ((size_t)g * NODES + node) * HID;
        feat[k * 388 + d]       = g_X0[gbase + d];
        feat[k * 388 + 128 + d] = g_X1[gbase + d];
        feat[k * 388 + 256 + d] = g_X2[gbase + d];
    }
    if (tid < KTOP) {
        feat[tid * 388 + 384] = x3[topi[tid]];
        feat[tid * 388 + 385] = 0.f;
        feat[tid * 388 + 386] = 0.f;
        feat[tid * 388 + 387] = 0.f;
    }
    __syncthreads();

    for (int o = tid; o < 640; o += 256) {
        int c = o & 15, kp = o >> 4;
        const float4* wr = (const float4*)(cw1s + c * 388);
        const float4* fr = (const float4*)(feat + kp * 388);
        unsigned long long s0 = 0ull, s1 = 0ull;
#pragma unroll 4
        for (int d = 0; d < 97; d++) {
            float4 w4 = wr[d], f4 = fr[d];
            ffma2(s0, pkf2(w4.x, w4.y), pkf2(f4.x, f4.y));
            ffma2(s1, pkf2(w4.z, w4.w), pkf2(f4.z, f4.w));
        }
        float a = cb1[c] + hsum2(s0) + hsum2(s1);
        y1[c * 40 + kp] = fmaxf(a, 0.f);
    }
    __syncthreads();

    for (int t = tid; t < 320; t += 256) {
        int c = t / 20, p = t % 20;
        mmp[t] = fmaxf(y1[c * 40 + 2 * p], y1[c * 40 + 2 * p + 1]);
    }
    __syncthreads();

    for (int t = tid; t < 512; t += 256) {
        int o2 = t >> 4, p = t & 15;
        float a = cb2[o2];
#pragma unroll
        for (int c = 0; c < 16; c++)
#pragma unroll
            for (int u = 0; u < 5; u++)
                a += cw2s[(o2 * 16 + c) * 5 + u] * mmp[c * 20 + p + u];
        flat[t] = fmaxf(a, 0.f);
    }
    __syncthreads();

    {
        int col = tid & 127, half = tid >> 7;
        float a = 0.f;
        const float* fp = flat + half * 256;
        const float* wp = mW1 + (size_t)(half * 256) * 128 + col;
#pragma unroll 8
        for (int i = 0; i < 256; i++) a += fp[i] * wp[(size_t)i * 128];
        y1[tid] = a;
    }
    __syncthreads();
    if (tid < 128) rr[tid] = fmaxf(y1[tid] + y1[tid + 128] + mb1[tid], 0.f);
    __syncthreads();

    if (tid < 32) {
        float s = 0.f;
#pragma unroll
        for (int q = 0; q < 4; q++) s += rr[tid + 32 * q] * mW2[tid + 32 * q];
        for (int off2 = 16; off2 > 0; off2 >>= 1)
            s += __shfl_down_sync(0xffffffffu, s, off2);
        if (tid == 0) out[g] = s + mb2[0];
    }
}

// ---------------- host ------------------------------------------------------
extern "C" void kernel_launch(void* const* d_in, const int* in_sizes, int n_in,
                              void* d_out, int out_size)
{
    const float* x    = (const float*)d_in[0];
    const int*   z    = (const int*)  d_in[1];
    const int*   ei   = (const int*)  d_in[2];
    const float* ztab = (const float*)d_in[4];
    const float* W0   = (const float*)d_in[5];
    const float* b0   = (const float*)d_in[6];
    const float* W1   = (const float*)d_in[7];
    const float* b1   = (const float*)d_in[8];
    const float* W2   = (const float*)d_in[9];
    const float* b2   = (const float*)d_in[10];
    const float* W3   = (const float*)d_in[11];
    const float* b3   = (const float*)d_in[12];
    const float* cw1  = (const float*)d_in[13];
    const float* cb1  = (const float*)d_in[14];
    const float* cw2  = (const float*)d_in[15];
    const float* cb2  = (const float*)d_in[16];
    const float* mW1  = (const float*)d_in[17];
    const float* mb1  = (const float*)d_in[18];
    const float* mW2  = (const float*)d_in[19];
    const float* mb2  = (const float*)d_in[20];
    float* out = (float*)d_out;

    float *T, *X0, *X1, *X2;
    cudaGetSymbolAddress((void**)&T,  g_T);
    cudaGetSymbolAddress((void**)&X0, g_X0);
    cudaGetSymbolAddress((void**)&X1, g_X1);
    cudaGetSymbolAddress((void**)&X2, g_X2);

    cudaFuncSetAttribute(agg_tanh, cudaFuncAttributeMaxDynamicSharedMemorySize, AGG_SMEM);
    cudaFuncSetAttribute(final_k,  cudaFuncAttributeMaxDynamicSharedMemorySize, 120 * 1024);

    const int GEMM_GRID = (NTOT + 127) / 128;

    build_csr<<<NG, 256>>>(ei);                                                        // 1

    gemm_tc<1, 256><<<GEMM_GRID, 256, GEMM_SMEM>>>(nullptr, z, ztab, x, W0, T, NTOT);  // 2
    agg_tanh<<<NG, 512, AGG_SMEM>>>(T, b0, X0);                                        // 3

    gemm_tc<0, 128><<<GEMM_GRID, 256, GEMM_SMEM>>>(X0, nullptr, nullptr, nullptr, W1, T, NTOT); // 4
    agg_tanh<<<NG, 512, AGG_SMEM>>>(T, b1, X1);                                        // 5

    gemm_tc<0, 128><<<GEMM_GRID, 256, GEMM_SMEM>>>(X1, nullptr, nullptr, nullptr, W2, T, NTOT); // 6 (ncu)
    agg_tanh<<<NG, 512, AGG_SMEM>>>(T, b2, X2);                                        // 7

    final_k<<<NG, 256, FINAL_SMEM_FLOATS * 4>>>(W3, b3, cw1, cb1, cw2, cb2,
                                                mW1, mb1, mW2, mb2, out);              // 8
}